// round 2
// baseline (speedup 1.0000x reference)
#include <cuda_runtime.h>
#include <math.h>

#define CCH 256
#define BAT 16
#define HDIM 16
#define SPATIAL 16384      // 128*128
#define BC (BAT*CCH)       // 4096

// Scratch (device globals — no allocations allowed)
__device__ float g_mean[BC];
__device__ float g_std[BC];
__device__ float g_mask[BC];

// ---------------------------------------------------------------------------
// Pass 1: per-(b,c) mean and biased std over 128x128 spatial plane.
// One block per (b,c); 256 threads, float4 loads (16 iters each).
// ---------------------------------------------------------------------------
__global__ void __launch_bounds__(256) stats_kernel(const float* __restrict__ x) {
    const int bc = blockIdx.x;
    const float4* __restrict__ xp =
        (const float4*)(x + (size_t)bc * SPATIAL);

    float s = 0.f, s2 = 0.f;
#pragma unroll
    for (int i = 0; i < SPATIAL / 4 / 256; i++) {
        float4 v = xp[i * 256 + threadIdx.x];
        s  += (v.x + v.y) + (v.z + v.w);
        s2 += (v.x * v.x + v.y * v.y) + (v.z * v.z + v.w * v.w);
    }
#pragma unroll
    for (int o = 16; o > 0; o >>= 1) {
        s  += __shfl_xor_sync(0xffffffffu, s,  o);
        s2 += __shfl_xor_sync(0xffffffffu, s2, o);
    }
    __shared__ float ws[8], ws2[8];
    const int w = threadIdx.x >> 5, l = threadIdx.x & 31;
    if (l == 0) { ws[w] = s; ws2[w] = s2; }
    __syncthreads();
    if (threadIdx.x == 0) {
        float ts = 0.f, ts2 = 0.f;
#pragma unroll
        for (int i = 0; i < 8; i++) { ts += ws[i]; ts2 += ws2[i]; }
        const float inv = 1.f / (float)SPATIAL;
        float mean = ts * inv;
        float var  = ts2 * inv - mean * mean;
        g_mean[bc] = mean;
        g_std[bc]  = sqrtf(fmaxf(var, 0.f));
    }
}

// ---------------------------------------------------------------------------
// Tiny MLP chain: SE(std), SE(mean), concat -> bottleneck -> SE -> sigmoid.
// One block per batch element (16 blocks x 256 threads). All weights read
// straight from global (a few KB, L2-resident after first block).
// ---------------------------------------------------------------------------
__global__ void __launch_bounds__(256) mlp_kernel(
    const float* __restrict__ sw1, const float* __restrict__ sb1,
    const float* __restrict__ sw2, const float* __restrict__ sb2,
    const float* __restrict__ mw1, const float* __restrict__ mb1,
    const float* __restrict__ mw2, const float* __restrict__ mb2,
    const float* __restrict__ bw,  const float* __restrict__ bb,
    const float* __restrict__ fw1, const float* __restrict__ fb1,
    const float* __restrict__ fw2, const float* __restrict__ fb2)
{
    const int b   = blockIdx.x;
    const int tid = threadIdx.x;

    __shared__ float sdesc[2 * CCH];   // [std(256) | mean(256)]
    __shared__ float h[2 * HDIM];      // [h_std(16) | h_mean(16)]
    __shared__ float fused[2 * CCH];   // [se_std(256) | se_mean(256)]
    __shared__ float bott[CCH];
    __shared__ float fh[HDIM];

    sdesc[tid]       = g_std[b * CCH + tid];
    sdesc[CCH + tid] = g_mean[b * CCH + tid];
    __syncthreads();

    // hidden layers of the two SE blocks (32 active threads)
    if (tid < 2 * HDIM) {
        const int hh = tid & (HDIM - 1);
        const float* w1 = (tid < HDIM) ? sw1 : mw1;
        const float* b1 = (tid < HDIM) ? sb1 : mb1;
        const float* d  = (tid < HDIM) ? sdesc : (sdesc + CCH);
        float acc = b1[hh];
#pragma unroll 8
        for (int c = 0; c < CCH; c++) acc = fmaf(w1[hh * CCH + c], d[c], acc);
        h[tid] = fmaxf(acc, 0.f);
    }
    __syncthreads();

    // SE output layers -> fused [512]
    {
        float a1 = sb2[tid], a2 = mb2[tid];
#pragma unroll
        for (int k = 0; k < HDIM; k++) {
            a1 = fmaf(sw2[tid * HDIM + k], h[k],        a1);
            a2 = fmaf(mw2[tid * HDIM + k], h[HDIM + k], a2);
        }
        fused[tid]       = a1;
        fused[CCH + tid] = a2;
    }
    __syncthreads();

    // bottleneck 512 -> 256 + relu
    {
        float acc = bb[tid];
#pragma unroll 8
        for (int d = 0; d < 2 * CCH; d++)
            acc = fmaf(bw[tid * (2 * CCH) + d], fused[d], acc);
        bott[tid] = fmaxf(acc, 0.f);
    }
    __syncthreads();

    // final SE hidden
    if (tid < HDIM) {
        float acc = fb1[tid];
#pragma unroll 8
        for (int c = 0; c < CCH; c++) acc = fmaf(fw1[tid * CCH + c], bott[c], acc);
        fh[tid] = fmaxf(acc, 0.f);
    }
    __syncthreads();

    // final SE output + sigmoid -> mask
    {
        float acc = fb2[tid];
#pragma unroll
        for (int k = 0; k < HDIM; k++) acc = fmaf(fw2[tid * HDIM + k], fh[k], acc);
        g_mask[b * CCH + tid] = 1.f / (1.f + expf(-acc));
    }
}

// ---------------------------------------------------------------------------
// Pass 2: out = x * mask[b,c]. Grid-stride, float4. Each float4 lies entirely
// within one (b,c) plane (16384 % 4 == 0), mask index = elem4 >> 12.
// ---------------------------------------------------------------------------
__global__ void __launch_bounds__(256) apply_kernel(const float* __restrict__ x,
                                                    float* __restrict__ out) {
    const size_t n4 = (size_t)BC * SPATIAL / 4;   // 16,777,216 float4s
    const float4* __restrict__ xp = (const float4*)x;
    float4* __restrict__ op = (float4*)out;
    for (size_t i = (size_t)blockIdx.x * blockDim.x + threadIdx.x;
         i < n4;
         i += (size_t)gridDim.x * blockDim.x) {
        const float m = __ldg(&g_mask[i >> 12]);
        float4 v = xp[i];
        v.x *= m; v.y *= m; v.z *= m; v.w *= m;
        op[i] = v;
    }
}

extern "C" void kernel_launch(void* const* d_in, const int* in_sizes, int n_in,
                              void* d_out, int out_size) {
    const float* x   = (const float*)d_in[0];
    const float* sw1 = (const float*)d_in[1];
    const float* sb1 = (const float*)d_in[2];
    const float* sw2 = (const float*)d_in[3];
    const float* sb2 = (const float*)d_in[4];
    const float* mw1 = (const float*)d_in[5];
    const float* mb1 = (const float*)d_in[6];
    const float* mw2 = (const float*)d_in[7];
    const float* mb2 = (const float*)d_in[8];
    const float* bw  = (const float*)d_in[9];
    const float* bb  = (const float*)d_in[10];
    const float* fw1 = (const float*)d_in[11];
    const float* fb1 = (const float*)d_in[12];
    const float* fw2 = (const float*)d_in[13];
    const float* fb2 = (const float*)d_in[14];
    float* out = (float*)d_out;

    stats_kernel<<<BC, 256>>>(x);
    mlp_kernel<<<BAT, 256>>>(sw1, sb1, sw2, sb2, mw1, mb1, mw2, mb2,
                             bw, bb, fw1, fb1, fw2, fb2);
    apply_kernel<<<8192, 256>>>(x, out);
}

// round 3
// speedup vs baseline: 1.3061x; 1.3061x over previous
#include <cuda_runtime.h>
#include <math.h>

#define CCH 256
#define BAT 16
#define HDIM 16
#define SPATIAL 16384      // 128*128
#define BC (BAT*CCH)       // 4096

// Scratch (device globals — no allocations allowed)
__device__ float g_mean[BC];
__device__ float g_std[BC];
__device__ float g_mask[BC];

__device__ __forceinline__ float warp_sum(float v) {
#pragma unroll
    for (int o = 16; o > 0; o >>= 1) v += __shfl_xor_sync(0xffffffffu, v, o);
    return v;
}

// ---------------------------------------------------------------------------
// Pass 1: per-(b,c) mean and biased std over 128x128 spatial plane.
// One block per (b,c); 256 threads, 16 fully-unrolled float4 loads each.
// (Measured 77.8% DRAM / 6.36 TB/s — unchanged.)
// ---------------------------------------------------------------------------
__global__ void __launch_bounds__(256) stats_kernel(const float* __restrict__ x) {
    const int bc = blockIdx.x;
    const float4* __restrict__ xp = (const float4*)(x + (size_t)bc * SPATIAL);

    float s = 0.f, s2 = 0.f;
#pragma unroll
    for (int i = 0; i < SPATIAL / 4 / 256; i++) {
        float4 v = xp[i * 256 + threadIdx.x];
        s  += (v.x + v.y) + (v.z + v.w);
        s2 += (v.x * v.x + v.y * v.y) + (v.z * v.z + v.w * v.w);
    }
    s  = warp_sum(s);
    s2 = warp_sum(s2);
    __shared__ float ws[8], ws2[8];
    const int w = threadIdx.x >> 5, l = threadIdx.x & 31;
    if (l == 0) { ws[w] = s; ws2[w] = s2; }
    __syncthreads();
    if (threadIdx.x == 0) {
        float ts = 0.f, ts2 = 0.f;
#pragma unroll
        for (int i = 0; i < 8; i++) { ts += ws[i]; ts2 += ws2[i]; }
        const float inv = 1.f / (float)SPATIAL;
        float mean = ts * inv;
        float var  = ts2 * inv - mean * mean;
        g_mean[bc] = mean;
        g_std[bc]  = sqrtf(fmaxf(var, 0.f));
    }
}

// ---------------------------------------------------------------------------
// Tiny MLP chain, now with warp-cooperative (coalesced) matvecs.
// One block per batch element (16 blocks x 256 threads).
// ---------------------------------------------------------------------------
__global__ void __launch_bounds__(256) mlp_kernel(
    const float* __restrict__ sw1, const float* __restrict__ sb1,
    const float* __restrict__ sw2, const float* __restrict__ sb2,
    const float* __restrict__ mw1, const float* __restrict__ mb1,
    const float* __restrict__ mw2, const float* __restrict__ mb2,
    const float* __restrict__ bw,  const float* __restrict__ bb,
    const float* __restrict__ fw1, const float* __restrict__ fb1,
    const float* __restrict__ fw2, const float* __restrict__ fb2)
{
    const int b   = blockIdx.x;
    const int tid = threadIdx.x;
    const int w   = tid >> 5, l = tid & 31;

    __shared__ float sdesc[2 * CCH];   // [std(256) | mean(256)]
    __shared__ float h[2 * HDIM];      // [h_std(16) | h_mean(16)]
    __shared__ float fused[2 * CCH];   // [se_std(256) | se_mean(256)]
    __shared__ float bott[CCH];
    __shared__ float fh[HDIM];

    sdesc[tid]       = g_std[b * CCH + tid];
    sdesc[CCH + tid] = g_mean[b * CCH + tid];
    __syncthreads();

    // --- SE hidden layers: 32 outputs (16 std + 16 mean), 256-dot each.
    // Warp w computes outputs w*4 .. w*4+3; lanes read coalesced.
#pragma unroll
    for (int j = 0; j < 4; j++) {
        const int o  = w * 4 + j;          // 0..31
        const int hh = o & (HDIM - 1);
        const float* w1 = (o < HDIM) ? sw1 : mw1;
        const float* d  = (o < HDIM) ? sdesc : (sdesc + CCH);
        float acc = 0.f;
#pragma unroll
        for (int k = 0; k < 8; k++)
            acc = fmaf(w1[hh * CCH + k * 32 + l], d[k * 32 + l], acc);
        acc = warp_sum(acc);
        if (l == 0) {
            const float bias = (o < HDIM) ? sb1[hh] : mb1[hh];
            h[o] = fmaxf(acc + bias, 0.f);
        }
    }
    __syncthreads();

    // --- SE output layers -> fused [512]. Thread per output, float4 rows.
    {
        float a1 = sb2[tid], a2 = mb2[tid];
        const float4* s2 = (const float4*)(sw2 + tid * HDIM);
        const float4* m2 = (const float4*)(mw2 + tid * HDIM);
#pragma unroll
        for (int q = 0; q < 4; q++) {
            float4 wa = s2[q], wb = m2[q];
            a1 = fmaf(wa.x, h[q * 4 + 0], a1);
            a1 = fmaf(wa.y, h[q * 4 + 1], a1);
            a1 = fmaf(wa.z, h[q * 4 + 2], a1);
            a1 = fmaf(wa.w, h[q * 4 + 3], a1);
            a2 = fmaf(wb.x, h[HDIM + q * 4 + 0], a2);
            a2 = fmaf(wb.y, h[HDIM + q * 4 + 1], a2);
            a2 = fmaf(wb.z, h[HDIM + q * 4 + 2], a2);
            a2 = fmaf(wb.w, h[HDIM + q * 4 + 3], a2);
        }
        fused[tid]       = a1;
        fused[CCH + tid] = a2;
    }
    __syncthreads();

    // --- Bottleneck 512 -> 256 + relu. Warp-cooperative, 2-way interleave.
    // Warp w computes outputs {w, w+8, w+16, ...} (32 outputs).
    for (int r = 0; r < 32; r += 2) {
        const int c0 = w + r * 8;
        const int c1 = w + (r + 1) * 8;
        float a0 = 0.f, a1 = 0.f;
#pragma unroll
        for (int k = 0; k < 16; k++) {
            const float f = fused[k * 32 + l];
            a0 = fmaf(bw[c0 * (2 * CCH) + k * 32 + l], f, a0);
            a1 = fmaf(bw[c1 * (2 * CCH) + k * 32 + l], f, a1);
        }
        a0 = warp_sum(a0);
        a1 = warp_sum(a1);
        if (l == 0) {
            bott[c0] = fmaxf(a0 + bb[c0], 0.f);
            bott[c1] = fmaxf(a1 + bb[c1], 0.f);
        }
    }
    __syncthreads();

    // --- Final SE hidden: 16 outputs, 256-dot. Warp w does outputs 2w, 2w+1.
#pragma unroll
    for (int j = 0; j < 2; j++) {
        const int o = w * 2 + j;           // 0..15
        float acc = 0.f;
#pragma unroll
        for (int k = 0; k < 8; k++)
            acc = fmaf(fw1[o * CCH + k * 32 + l], bott[k * 32 + l], acc);
        acc = warp_sum(acc);
        if (l == 0) fh[o] = fmaxf(acc + fb1[o], 0.f);
    }
    __syncthreads();

    // --- Final SE output + sigmoid -> mask. Thread per output, float4 row.
    {
        float acc = fb2[tid];
        const float4* f2 = (const float4*)(fw2 + tid * HDIM);
#pragma unroll
        for (int q = 0; q < 4; q++) {
            float4 wv = f2[q];
            acc = fmaf(wv.x, fh[q * 4 + 0], acc);
            acc = fmaf(wv.y, fh[q * 4 + 1], acc);
            acc = fmaf(wv.z, fh[q * 4 + 2], acc);
            acc = fmaf(wv.w, fh[q * 4 + 3], acc);
        }
        g_mask[b * CCH + tid] = 1.f / (1.f + expf(-acc));
    }
}

// ---------------------------------------------------------------------------
// Pass 2: out = x * mask[b,c]. Each block owns 2048 consecutive float4s =
// exactly half of one (b,c) plane -> single mask scalar per block.
// 8 fully-unrolled, front-batched loads per thread.
// ---------------------------------------------------------------------------
__global__ void __launch_bounds__(256) apply_kernel(const float* __restrict__ x,
                                                    float* __restrict__ out) {
    const size_t base = (size_t)blockIdx.x * 2048 + threadIdx.x;
    const float m = g_mask[blockIdx.x >> 1];
    const float4* __restrict__ xp = (const float4*)x + base;
    float4* __restrict__ op = (float4*)out + base;

    float4 v[8];
#pragma unroll
    for (int i = 0; i < 8; i++) v[i] = xp[i * 256];
#pragma unroll
    for (int i = 0; i < 8; i++) {
        float4 t = v[i];
        t.x *= m; t.y *= m; t.z *= m; t.w *= m;
        op[i * 256] = t;
    }
}

extern "C" void kernel_launch(void* const* d_in, const int* in_sizes, int n_in,
                              void* d_out, int out_size) {
    const float* x   = (const float*)d_in[0];
    const float* sw1 = (const float*)d_in[1];
    const float* sb1 = (const float*)d_in[2];
    const float* sw2 = (const float*)d_in[3];
    const float* sb2 = (const float*)d_in[4];
    const float* mw1 = (const float*)d_in[5];
    const float* mb1 = (const float*)d_in[6];
    const float* mw2 = (const float*)d_in[7];
    const float* mb2 = (const float*)d_in[8];
    const float* bw  = (const float*)d_in[9];
    const float* bb  = (const float*)d_in[10];
    const float* fw1 = (const float*)d_in[11];
    const float* fb1 = (const float*)d_in[12];
    const float* fw2 = (const float*)d_in[13];
    const float* fb2 = (const float*)d_in[14];
    float* out = (float*)d_out;

    stats_kernel<<<BC, 256>>>(x);
    mlp_kernel<<<BAT, 256>>>(sw1, sb1, sw2, sb2, mw1, mb1, mw2, mb2,
                             bw, bb, fw1, fb1, fw2, fb2);
    apply_kernel<<<BC * 2, 256>>>(x, out);
}

// round 4
// speedup vs baseline: 1.5202x; 1.1639x over previous
#include <cuda_runtime.h>
#include <math.h>

#define CCH 256
#define BAT 16
#define HDIM 16
#define SPATIAL 16384      // 128*128
#define BC (BAT*CCH)       // 4096

// Scratch (device globals — no allocations allowed)
__device__ float g_mean[BC];
__device__ float g_std[BC];
__device__ float g_mask[BC];

__device__ __forceinline__ float warp_sum(float v) {
#pragma unroll
    for (int o = 16; o > 0; o >>= 1) v += __shfl_xor_sync(0xffffffffu, v, o);
    return v;
}

__device__ __forceinline__ float dot4(float4 a, float4 b, float acc) {
    acc = fmaf(a.x, b.x, acc);
    acc = fmaf(a.y, b.y, acc);
    acc = fmaf(a.z, b.z, acc);
    return fmaf(a.w, b.w, acc);
}

// ---------------------------------------------------------------------------
// Pass 1: per-(b,c) mean and biased std over 128x128 spatial plane.
// One block per (b,c); 256 threads, 16 fully-unrolled float4 loads each.
// (Measured 81% DRAM / 6.5 TB/s — unchanged.)
// ---------------------------------------------------------------------------
__global__ void __launch_bounds__(256) stats_kernel(const float* __restrict__ x) {
    const int bc = blockIdx.x;
    const float4* __restrict__ xp = (const float4*)(x + (size_t)bc * SPATIAL);

    float s = 0.f, s2 = 0.f;
#pragma unroll
    for (int i = 0; i < SPATIAL / 4 / 256; i++) {
        float4 v = __ldcs(&xp[i * 256 + threadIdx.x]);
        s  += (v.x + v.y) + (v.z + v.w);
        s2 += (v.x * v.x + v.y * v.y) + (v.z * v.z + v.w * v.w);
    }
    s  = warp_sum(s);
    s2 = warp_sum(s2);
    __shared__ float ws[8], ws2[8];
    const int w = threadIdx.x >> 5, l = threadIdx.x & 31;
    if (l == 0) { ws[w] = s; ws2[w] = s2; }
    __syncthreads();
    if (threadIdx.x == 0) {
        float ts = 0.f, ts2 = 0.f;
#pragma unroll
        for (int i = 0; i < 8; i++) { ts += ws[i]; ts2 += ws2[i]; }
        const float inv = 1.f / (float)SPATIAL;
        float mean = ts * inv;
        float var  = ts2 * inv - mean * mean;
        g_mean[bc] = mean;
        g_std[bc]  = sqrtf(fmaxf(var, 0.f));
    }
}

// ---------------------------------------------------------------------------
// Tiny MLP chain, warp-cooperative matvecs with float4 weight loads.
// One block per batch element (16 blocks x 256 threads).
// ---------------------------------------------------------------------------
__global__ void __launch_bounds__(256) mlp_kernel(
    const float* __restrict__ sw1, const float* __restrict__ sb1,
    const float* __restrict__ sw2, const float* __restrict__ sb2,
    const float* __restrict__ mw1, const float* __restrict__ mb1,
    const float* __restrict__ mw2, const float* __restrict__ mb2,
    const float* __restrict__ bw,  const float* __restrict__ bb,
    const float* __restrict__ fw1, const float* __restrict__ fb1,
    const float* __restrict__ fw2, const float* __restrict__ fb2)
{
    const int b   = blockIdx.x;
    const int tid = threadIdx.x;
    const int w   = tid >> 5, l = tid & 31;

    __shared__ float sdesc[2 * CCH];   // [std(256) | mean(256)]
    __shared__ float h[2 * HDIM];      // [h_std(16) | h_mean(16)]
    __shared__ float fused[2 * CCH];   // [se_std(256) | se_mean(256)]
    __shared__ float bott[CCH];
    __shared__ float fh[HDIM];

    sdesc[tid]       = g_std[b * CCH + tid];
    sdesc[CCH + tid] = g_mean[b * CCH + tid];
    __syncthreads();

    const float4* sdesc4 = (const float4*)sdesc;   // 64 float4s std, then mean

    // --- SE hidden layers: 32 outputs (16 std + 16 mean), 256-dot each.
    // Warp w computes outputs w*4 .. w*4+3; lane l reads float4 (coalesced).
#pragma unroll
    for (int j = 0; j < 4; j++) {
        const int o  = w * 4 + j;          // 0..31
        const int hh = o & (HDIM - 1);
        const float4* w1 = (const float4*)(((o < HDIM) ? sw1 : mw1) + hh * CCH);
        const float4* d  = (o < HDIM) ? sdesc4 : (sdesc4 + CCH / 4);
        float acc = 0.f;
#pragma unroll
        for (int k = 0; k < 2; k++)
            acc = dot4(w1[k * 32 + l], d[k * 32 + l], acc);
        acc = warp_sum(acc);
        if (l == 0) {
            const float bias = (o < HDIM) ? sb1[hh] : mb1[hh];
            h[o] = fmaxf(acc + bias, 0.f);
        }
    }
    __syncthreads();

    // --- SE output layers -> fused [512]. Thread per output, float4 rows.
    {
        float a1 = sb2[tid], a2 = mb2[tid];
        const float4* s2 = (const float4*)(sw2 + tid * HDIM);
        const float4* m2 = (const float4*)(mw2 + tid * HDIM);
        const float4* h4a = (const float4*)h;
        const float4* h4b = (const float4*)(h + HDIM);
#pragma unroll
        for (int q = 0; q < 4; q++) {
            a1 = dot4(s2[q], h4a[q], a1);
            a2 = dot4(m2[q], h4b[q], a2);
        }
        fused[tid]       = a1;
        fused[CCH + tid] = a2;
    }
    __syncthreads();

    // --- Bottleneck 512 -> 256 + relu. Warp-cooperative, float4 loads,
    // 2-way output interleave. Warp w computes outputs {w + r*8}.
    const float4* fused4 = (const float4*)fused;   // 128 float4s
    for (int r = 0; r < 32; r += 2) {
        const int c0 = w + r * 8;
        const int c1 = w + (r + 1) * 8;
        const float4* b0 = (const float4*)(bw + c0 * (2 * CCH));
        const float4* b1 = (const float4*)(bw + c1 * (2 * CCH));
        float a0 = 0.f, a1 = 0.f;
#pragma unroll
        for (int k = 0; k < 4; k++) {
            const float4 f = fused4[k * 32 + l];
            a0 = dot4(b0[k * 32 + l], f, a0);
            a1 = dot4(b1[k * 32 + l], f, a1);
        }
        a0 = warp_sum(a0);
        a1 = warp_sum(a1);
        if (l == 0) {
            bott[c0] = fmaxf(a0 + bb[c0], 0.f);
            bott[c1] = fmaxf(a1 + bb[c1], 0.f);
        }
    }
    __syncthreads();

    // --- Final SE hidden: 16 outputs, 256-dot. Warp w does outputs 2w, 2w+1.
    const float4* bott4 = (const float4*)bott;     // 64 float4s
#pragma unroll
    for (int j = 0; j < 2; j++) {
        const int o = w * 2 + j;           // 0..15
        const float4* w1 = (const float4*)(fw1 + o * CCH);
        float acc = 0.f;
#pragma unroll
        for (int k = 0; k < 2; k++)
            acc = dot4(w1[k * 32 + l], bott4[k * 32 + l], acc);
        acc = warp_sum(acc);
        if (l == 0) fh[o] = fmaxf(acc + fb1[o], 0.f);
    }
    __syncthreads();

    // --- Final SE output + sigmoid -> mask. Thread per output, float4 row.
    {
        float acc = fb2[tid];
        const float4* f2  = (const float4*)(fw2 + tid * HDIM);
        const float4* fh4 = (const float4*)fh;
#pragma unroll
        for (int q = 0; q < 4; q++) acc = dot4(f2[q], fh4[q], acc);
        g_mask[b * CCH + tid] = 1.f / (1.f + expf(-acc));
    }
}

// ---------------------------------------------------------------------------
// Pass 2: out = x * mask[b,c]. Each block owns 2048 consecutive float4s =
// exactly half of one (b,c) plane -> single mask scalar per block.
// Streaming loads (__ldcs) and streaming stores (__stcs): neither stream is
// ever re-referenced, keep them from thrashing L2.
// ---------------------------------------------------------------------------
__global__ void __launch_bounds__(256) apply_kernel(const float* __restrict__ x,
                                                    float* __restrict__ out) {
    const size_t base = (size_t)blockIdx.x * 2048 + threadIdx.x;
    const float m = g_mask[blockIdx.x >> 1];
    const float4* __restrict__ xp = (const float4*)x + base;
    float4* __restrict__ op = (float4*)out + base;

    float4 v[8];
#pragma unroll
    for (int i = 0; i < 8; i++) v[i] = __ldcs(&xp[i * 256]);
#pragma unroll
    for (int i = 0; i < 8; i++) {
        float4 t = v[i];
        t.x *= m; t.y *= m; t.z *= m; t.w *= m;
        __stcs(&op[i * 256], t);
    }
}

extern "C" void kernel_launch(void* const* d_in, const int* in_sizes, int n_in,
                              void* d_out, int out_size) {
    const float* x   = (const float*)d_in[0];
    const float* sw1 = (const float*)d_in[1];
    const float* sb1 = (const float*)d_in[2];
    const float* sw2 = (const float*)d_in[3];
    const float* sb2 = (const float*)d_in[4];
    const float* mw1 = (const float*)d_in[5];
    const float* mb1 = (const float*)d_in[6];
    const float* mw2 = (const float*)d_in[7];
    const float* mb2 = (const float*)d_in[8];
    const float* bw  = (const float*)d_in[9];
    const float* bb  = (const float*)d_in[10];
    const float* fw1 = (const float*)d_in[11];
    const float* fb1 = (const float*)d_in[12];
    const float* fw2 = (const float*)d_in[13];
    const float* fb2 = (const float*)d_in[14];
    float* out = (float*)d_out;

    stats_kernel<<<BC, 256>>>(x);
    mlp_kernel<<<BAT, 256>>>(sw1, sb1, sw2, sb2, mw1, mb1, mw2, mb2,
                             bw, bb, fw1, fb1, fw2, fb2);
    apply_kernel<<<BC * 2, 256>>>(x, out);
}